// round 6
// baseline (speedup 1.0000x reference)
#include <cuda_runtime.h>

// Problem constants (fixed by the dataset)
#define BS 8
#define NQ 1500
#define NPRED (BS * NQ)   // 12000
#define NTGT 4800
#define BJ 256            // targets per block tile (2 subtiles of 128)
#define PRW 12            // preds per warp
#define BI (8 * PRW)      // 96 preds per block; 12000 % 96 == 0

// C[i,j] = 5*|px_i - tx_j| + 5*|py_i - ty_j| + sp_i - t0_j*x0_i - t1_j*x1_i
// sp_i = softplus(x0_i) + softplus(x1_i)

__global__ __launch_bounds__(256)
void hungarian_cost_kernel(const float* __restrict__ pred_logits,
                           const float* __restrict__ pred_points,
                           const float* __restrict__ tgt_labels,
                           const float* __restrict__ tgt_points,
                           float* __restrict__ out)
{
    __shared__ float  s_tx[BJ], s_ty[BJ], s_t0[BJ], s_t1[BJ];  // target SoA (scaled)
    __shared__ float4 s_pred[BI];   // {5*px, 5*py, x0, x1}
    __shared__ float  s_sp[BI];     // softplus sum

    const int lane   = threadIdx.x;
    const int w      = threadIdx.y;          // warp id 0..7
    const int tid    = w * 32 + lane;
    const int j_base = blockIdx.x * BJ;
    const int i_base = blockIdx.y * BI;

    // ---- Prologue: stage 256 targets (all threads) + 96 preds (first 96) ----
    {
        const int jt = j_base + tid;
        float2 p = make_float2(0.f, 0.f), l2 = make_float2(0.f, 0.f);
        if (jt < NTGT) {
            p  = ((const float2*)tgt_points)[jt];
            l2 = ((const float2*)tgt_labels)[jt];
        }
        s_tx[tid] = 5.0f * p.x;
        s_ty[tid] = 5.0f * p.y;
        s_t0[tid] = l2.x;
        s_t1[tid] = l2.y;
    }
    if (tid < BI) {
        const int i = i_base + tid;          // always < NPRED (12000 % 96 == 0)
        const float2 x = ((const float2*)pred_logits)[i];
        const float2 p = ((const float2*)pred_points)[i];
        const float sp = fmaxf(x.x, 0.f) + log1pf(expf(-fabsf(x.x)))
                       + fmaxf(x.y, 0.f) + log1pf(expf(-fabsf(x.y)));
        s_pred[tid] = make_float4(5.0f * p.x, 5.0f * p.y, x.x, x.y);
        s_sp[tid]   = sp;
    }

    __syncthreads();

    // Subtile A: j0a = j_base + lane*4         (always valid: grid covers it)
    // Subtile B: j0b = j_base + 128 + lane*4   (partial on last tile)
    const int j0a = j_base + lane * 4;
    const int j0b = j0a + 128;
    const bool validB = (j0b < NTGT);   // last tile: 4800-4608-128=64 -> lanes 0..15

    // ---- Hoist this lane's 8 targets: conflict-free LDS.128 from SoA ----
    const float4 vtxA = ((const float4*)s_tx)[lane];
    const float4 vtyA = ((const float4*)s_ty)[lane];
    const float4 vt0A = ((const float4*)s_t0)[lane];
    const float4 vt1A = ((const float4*)s_t1)[lane];
    const float4 vtxB = ((const float4*)s_tx)[32 + lane];
    const float4 vtyB = ((const float4*)s_ty)[32 + lane];
    const float4 vt0B = ((const float4*)s_t0)[32 + lane];
    const float4 vt1B = ((const float4*)s_t1)[32 + lane];

    float* const obase = out + (size_t)(i_base + w * PRW) * NTGT + j0a;

    // ---- Main loop: 12 preds per warp, 256 outputs per pred per warp ----
    #pragma unroll
    for (int p4 = 0; p4 < PRW / 4; p4++) {
        const float4 sp4 = ((const float4*)s_sp)[w * (PRW / 4) + p4];  // broadcast
        #pragma unroll
        for (int q = 0; q < 4; q++) {
            const int    pl = p4 * 4 + q;
            const float4 pr = s_pred[w * PRW + pl];     // broadcast LDS.128
            const float  sp = (q == 0) ? sp4.x : (q == 1) ? sp4.y
                            : (q == 2) ? sp4.z : sp4.w;

            float4 rA, rB;
            // subtile A
            rA.x = fabsf(pr.x - vtxA.x) + fabsf(pr.y - vtyA.x)
                 + fmaf(-vt1A.x, pr.w, fmaf(-vt0A.x, pr.z, sp));
            rA.y = fabsf(pr.x - vtxA.y) + fabsf(pr.y - vtyA.y)
                 + fmaf(-vt1A.y, pr.w, fmaf(-vt0A.y, pr.z, sp));
            rA.z = fabsf(pr.x - vtxA.z) + fabsf(pr.y - vtyA.z)
                 + fmaf(-vt1A.z, pr.w, fmaf(-vt0A.z, pr.z, sp));
            rA.w = fabsf(pr.x - vtxA.w) + fabsf(pr.y - vtyA.w)
                 + fmaf(-vt1A.w, pr.w, fmaf(-vt0A.w, pr.z, sp));
            // subtile B
            rB.x = fabsf(pr.x - vtxB.x) + fabsf(pr.y - vtyB.x)
                 + fmaf(-vt1B.x, pr.w, fmaf(-vt0B.x, pr.z, sp));
            rB.y = fabsf(pr.x - vtxB.y) + fabsf(pr.y - vtyB.y)
                 + fmaf(-vt1B.y, pr.w, fmaf(-vt0B.y, pr.z, sp));
            rB.z = fabsf(pr.x - vtxB.z) + fabsf(pr.y - vtyB.z)
                 + fmaf(-vt1B.z, pr.w, fmaf(-vt0B.z, pr.z, sp));
            rB.w = fabsf(pr.x - vtxB.w) + fabsf(pr.y - vtyB.w)
                 + fmaf(-vt1B.w, pr.w, fmaf(-vt0B.w, pr.z, sp));

            float* const orow = obase + (size_t)pl * NTGT;
            __stcs((float4*)orow, rA);                       // coalesced 512B/warp
            if (validB) __stcs((float4*)(orow + 128), rB);   // coalesced 512B/warp
        }
    }
}

extern "C" void kernel_launch(void* const* d_in, const int* in_sizes, int n_in,
                              void* d_out, int out_size)
{
    const float* pred_logits = (const float*)d_in[0];  // (8,1500,2)
    const float* pred_points = (const float*)d_in[1];  // (8,1500,2)
    const float* tgt_labels  = (const float*)d_in[2];  // (4800,2)
    const float* tgt_points  = (const float*)d_in[3];  // (4800,2)
    float* out = (float*)d_out;                        // (8,1500,4800)

    dim3 block(32, 8);
    dim3 grid((NTGT + BJ - 1) / BJ, NPRED / BI);       // (19, 125)
    hungarian_cost_kernel<<<grid, block>>>(pred_logits, pred_points,
                                           tgt_labels, tgt_points, out);
}